// round 5
// baseline (speedup 1.0000x reference)
#include <cuda_runtime.h>
#include <math.h>

// Shapes
#define NB 256            // batch
#define NF 4              // frames
#define PIX4 9408         // float4 per frame (3*112*112/4)
#define TILES_PER_B 8
#define NTILES (NB * TILES_PER_B)       // 2048 img tiles
#define TILE4 (PIX4 / TILES_PER_B)      // 1176 float4 per tile
#define TPB 256
#define GRID 592                        // 148 SMs * 4 CTAs — one resident wave
#define NITEMS (NB + NTILES)            // 256 feat items + 2048 img items

// Scratch: each slot written exactly once per launch — no zeroing needed.
__device__ float g_part[NTILES * 3];    // per-tile squared-diff partials
__device__ int   g_neqp[NTILES * 3];    // per-tile any-neq flags
__device__ float g_cos[NB * 3];         // per-batch cosine similarities
__device__ int   g_ctr;                 // zero at process start; reset by epilogue

__device__ __forceinline__ void accum_group(const float4& f0, const float4& f1,
                                            const float4& f2, const float4& f3,
                                            float& s1, float& s2, float& s3,
                                            int& nq1, int& nq2, int& nq3) {
    float dx, dy, dz, dw;
    dx = f1.x - f0.x; dy = f1.y - f0.y; dz = f1.z - f0.z; dw = f1.w - f0.w;
    s1 += dx * dx + dy * dy + dz * dz + dw * dw;
    nq1 |= (f1.x != f0.x) | (f1.y != f0.y) | (f1.z != f0.z) | (f1.w != f0.w);

    dx = f2.x - f1.x; dy = f2.y - f1.y; dz = f2.z - f1.z; dw = f2.w - f1.w;
    s2 += dx * dx + dy * dy + dz * dz + dw * dw;
    nq2 |= (f2.x != f0.x) | (f2.y != f0.y) | (f2.z != f0.z) | (f2.w != f0.w);

    dx = f3.x - f2.x; dy = f3.y - f2.y; dz = f3.z - f2.z; dw = f3.w - f2.w;
    s3 += dx * dx + dy * dy + dz * dz + dw * dw;
    nq3 |= (f3.x != f0.x) | (f3.y != f0.y) | (f3.z != f0.z) | (f3.w != f0.w);
}

__global__ void fused_kernel(const float4* __restrict__ img,
                             const float* __restrict__ feat,
                             const float* __restrict__ feat_norm,
                             float* __restrict__ out) {
    __shared__ float sm7[7][TPB / 32];
    __shared__ int   smn[TPB / 32];
    __shared__ int   s_last;

    const int w = threadIdx.x >> 5;
    const int l = threadIdx.x & 31;

    for (int item = blockIdx.x; item < NITEMS; item += GRID) {
        if (item < NB) {
            // ------------- feat item: per-batch norms/dots/cos + weight ----
            const int b = item;
            const float* fb = feat + (size_t)b * (NF * 512);

            float n0 = 0.f, n1 = 0.f, n2 = 0.f, n3 = 0.f;
            float d01 = 0.f, d12 = 0.f, d23 = 0.f;
            #pragma unroll
            for (int k = 0; k < 2; k++) {
                int i = threadIdx.x + k * TPB;
                float a = fb[i];
                float c = fb[512 + i];
                float d = fb[1024 + i];
                float e = fb[1536 + i];
                n0 += a * a; n1 += c * c; n2 += d * d; n3 += e * e;
                d01 += a * c; d12 += c * d; d23 += d * e;
            }
            #pragma unroll
            for (int off = 16; off; off >>= 1) {
                n0  += __shfl_down_sync(0xffffffffu, n0,  off);
                n1  += __shfl_down_sync(0xffffffffu, n1,  off);
                n2  += __shfl_down_sync(0xffffffffu, n2,  off);
                n3  += __shfl_down_sync(0xffffffffu, n3,  off);
                d01 += __shfl_down_sync(0xffffffffu, d01, off);
                d12 += __shfl_down_sync(0xffffffffu, d12, off);
                d23 += __shfl_down_sync(0xffffffffu, d23, off);
            }
            if (l == 0) {
                sm7[0][w] = n0;  sm7[1][w] = n1;  sm7[2][w] = n2;  sm7[3][w] = n3;
                sm7[4][w] = d01; sm7[5][w] = d12; sm7[6][w] = d23;
            }
            __syncthreads();
            if (threadIdx.x == 0) {
                float v[7];
                #pragma unroll
                for (int j = 0; j < 7; j++) {
                    float s = 0.f;
                    #pragma unroll
                    for (int k = 0; k < TPB / 32; k++) s += sm7[j][k];
                    v[j] = s;
                }
                float na[4];
                #pragma unroll
                for (int j = 0; j < 4; j++) na[j] = fmaxf(sqrtf(v[j]), 1e-8f);
                #pragma unroll
                for (int j = 0; j < 3; j++)
                    g_cos[b * 3 + j] = v[4 + j] / (na[j] * na[j + 1]);

                const float fn0 = feat_norm[b * NF];     // feat_norm[b,0,0]
                const bool cond = fn0 > 0.0f;            // TAO = 0
                const float wgt = 1.0f / (expf(fn0) + 1e-10f);
                out[1 + b] = cond ? wgt : 0.0f;          // also encodes cond (wgt>0)
            }
            __syncthreads();   // sm7 reuse safety for next item
        } else {
            // ------------- img tile item: squared diffs + neq flags --------
            const int t = item - NB;                     // tile index
            const int b = t >> 3;                        // /TILES_PER_B
            const int chunk = t & (TILES_PER_B - 1);
            const float4* base = img + (size_t)b * (NF * PIX4);

            float s1 = 0.f, s2 = 0.f, s3 = 0.f;
            int nq1 = 0, nq2 = 0, nq3 = 0;
            const int end = (chunk + 1) * TILE4;

            // 2x unrolled: 8 independent LDG.128 in flight before compute.
            for (int i = chunk * TILE4 + threadIdx.x; i < end; i += 2 * TPB) {
                const int i2 = i + TPB;
                const bool has2 = i2 < end;

                float4 a0 = __ldcs(base + i);
                float4 a1 = __ldcs(base + PIX4 + i);
                float4 a2 = __ldcs(base + 2 * PIX4 + i);
                float4 a3 = __ldcs(base + 3 * PIX4 + i);
                float4 b0, b1, b2, b3;
                if (has2) {
                    b0 = __ldcs(base + i2);
                    b1 = __ldcs(base + PIX4 + i2);
                    b2 = __ldcs(base + 2 * PIX4 + i2);
                    b3 = __ldcs(base + 3 * PIX4 + i2);
                }

                accum_group(a0, a1, a2, a3, s1, s2, s3, nq1, nq2, nq3);
                if (has2)
                    accum_group(b0, b1, b2, b3, s1, s2, s3, nq1, nq2, nq3);
            }

            // Fused reduction: 3 float sums + packed neq bits.
            int nqp = nq1 | (nq2 << 1) | (nq3 << 2);
            #pragma unroll
            for (int off = 16; off; off >>= 1) {
                s1 += __shfl_down_sync(0xffffffffu, s1, off);
                s2 += __shfl_down_sync(0xffffffffu, s2, off);
                s3 += __shfl_down_sync(0xffffffffu, s3, off);
                nqp |= __shfl_down_sync(0xffffffffu, nqp, off);
            }
            if (l == 0) { sm7[0][w] = s1; sm7[1][w] = s2; sm7[2][w] = s3; smn[w] = nqp; }
            __syncthreads();
            if (threadIdx.x < 3) {
                float s = 0.f;
                int nq = 0;
                #pragma unroll
                for (int k = 0; k < TPB / 32; k++) { s += sm7[threadIdx.x][k]; nq |= smn[k]; }
                g_part[t * 3 + threadIdx.x] = s;
                g_neqp[t * 3 + threadIdx.x] = (nq >> threadIdx.x) & 1;
            }
            __syncthreads();   // sm7/smn reuse safety for next item
        }
    }

    // ---------------- elect last-finished block for the epilogue ----------
    if (threadIdx.x == 0) {
        __threadfence();
        int old = atomicAdd(&g_ctr, 1);
        s_last = (old == GRID - 1) ? 1 : 0;
    }
    __syncthreads();
    if (!s_last) return;

    __threadfence();  // acquire: make all other blocks' writes visible

    // thread b handles batch b (256 threads == NB)
    const int b = threadIdx.x;
    float pen = 0.0f;
    {
        const float outw = out[1 + b];   // cond ? wgt : 0
        #pragma unroll
        for (int j = 0; j < 3; j++) {
            float dsq = 0.f;
            int nq = 0;
            #pragma unroll
            for (int c = 0; c < TILES_PER_B; c++) {
                dsq += g_part[(b * TILES_PER_B + c) * 3 + j];
                nq |= g_neqp[(b * TILES_PER_B + c) * 3 + j];
            }
            float img_diff = sqrtf(dsq) + 1e-10f;
            float ratio = (1.0f - g_cos[b * 3 + j]) / img_diff;  // LIP = 0
            float term = fmaxf(ratio, 0.0f) * outw;              // SQUARED = false
            if (nq) pen += term;                                 // outw==0 covers !cond
        }
    }
    #pragma unroll
    for (int off = 16; off; off >>= 1)
        pen += __shfl_down_sync(0xffffffffu, pen, off);

    __shared__ float smr[TPB / 32];
    if (l == 0) smr[w] = pen;
    __syncthreads();
    if (threadIdx.x == 0) {
        float s = 0.f;
        #pragma unroll
        for (int k = 0; k < TPB / 32; k++) s += smr[k];
        out[0] = s * (1.0f / (float)NB);   // LAMB_LIP = 1
        g_ctr = 0;                          // reset for next graph replay
    }
}

extern "C" void kernel_launch(void* const* d_in, const int* in_sizes, int n_in,
                              void* d_out, int out_size) {
    const float4* img = (const float4*)d_in[0];
    const float* feat = (const float*)d_in[1];
    const float* feat_norm = (const float*)d_in[2];
    float* out = (float*)d_out;

    fused_kernel<<<GRID, TPB>>>(img, feat, feat_norm, out);
}

// round 9
// speedup vs baseline: 1.0713x; 1.0713x over previous
#include <cuda_runtime.h>
#include <math.h>

// Shapes
#define NB 256            // batch
#define NF 4              // frames
#define PIX4 9408         // float4 per frame (3*112*112/4)
#define TOT (NB * PIX4)   // 2408448 global float4 work items
#define TPB 256
#define CH 4096           // float4 per block: TOT = 588 * 4096 exactly
#define GRID 588          // <= 592 (148 SMs * 4 CTAs) — exactly one wave

// Scratch. g_part/g_neq: zero at process start; epilogue re-zeroes after use.
// g_cos: written exactly once per launch (no init needed).
__device__ float g_part[NB * 3];
__device__ int   g_neq[NB];        // 3-bit mask per batch
__device__ float g_cos[NB * 3];
__device__ int   g_ctr;

__device__ __forceinline__ void group_terms(const float4& f0, const float4& f1,
                                            const float4& f2, const float4& f3,
                                            float& t1, float& t2, float& t3, int& m) {
    float dx, dy, dz, dw;
    dx = f1.x - f0.x; dy = f1.y - f0.y; dz = f1.z - f0.z; dw = f1.w - f0.w;
    t1 = dx * dx + dy * dy + dz * dz + dw * dw;
    m  = (f1.x != f0.x) | (f1.y != f0.y) | (f1.z != f0.z) | (f1.w != f0.w);

    dx = f2.x - f1.x; dy = f2.y - f1.y; dz = f2.z - f1.z; dw = f2.w - f1.w;
    t2 = dx * dx + dy * dy + dz * dz + dw * dw;
    m |= ((f2.x != f0.x) | (f2.y != f0.y) | (f2.z != f0.z) | (f2.w != f0.w)) << 1;

    dx = f3.x - f2.x; dy = f3.y - f2.y; dz = f3.z - f2.z; dw = f3.w - f2.w;
    t3 = dx * dx + dy * dy + dz * dz + dw * dw;
    m |= ((f3.x != f0.x) | (f3.y != f0.y) | (f3.z != f0.z) | (f3.w != f0.w)) << 2;
}

__global__ void __launch_bounds__(TPB, 4)
fused_kernel(const float4* __restrict__ img,
             const float* __restrict__ feat,
             const float* __restrict__ feat_norm,
             float* __restrict__ out) {
    __shared__ float sm7[7][TPB / 32];
    __shared__ int   smn[TPB / 32];
    __shared__ int   s_last;

    const int w = threadIdx.x >> 5;
    const int l = threadIdx.x & 31;

    // ---------------- feat prelude (blocks 0..255 only) -------------------
    if (blockIdx.x < NB) {
        const int b = blockIdx.x;
        const float* fb = feat + (size_t)b * (NF * 512);

        float n0 = 0.f, n1 = 0.f, n2 = 0.f, n3 = 0.f;
        float d01 = 0.f, d12 = 0.f, d23 = 0.f;
        #pragma unroll
        for (int k = 0; k < 2; k++) {
            int i = threadIdx.x + k * TPB;
            float a = fb[i];
            float c = fb[512 + i];
            float d = fb[1024 + i];
            float e = fb[1536 + i];
            n0 += a * a; n1 += c * c; n2 += d * d; n3 += e * e;
            d01 += a * c; d12 += c * d; d23 += d * e;
        }
        #pragma unroll
        for (int off = 16; off; off >>= 1) {
            n0  += __shfl_down_sync(0xffffffffu, n0,  off);
            n1  += __shfl_down_sync(0xffffffffu, n1,  off);
            n2  += __shfl_down_sync(0xffffffffu, n2,  off);
            n3  += __shfl_down_sync(0xffffffffu, n3,  off);
            d01 += __shfl_down_sync(0xffffffffu, d01, off);
            d12 += __shfl_down_sync(0xffffffffu, d12, off);
            d23 += __shfl_down_sync(0xffffffffu, d23, off);
        }
        if (l == 0) {
            sm7[0][w] = n0;  sm7[1][w] = n1;  sm7[2][w] = n2;  sm7[3][w] = n3;
            sm7[4][w] = d01; sm7[5][w] = d12; sm7[6][w] = d23;
        }
        __syncthreads();
        if (threadIdx.x == 0) {
            float v[7];
            #pragma unroll
            for (int j = 0; j < 7; j++) {
                float s = 0.f;
                #pragma unroll
                for (int k = 0; k < TPB / 32; k++) s += sm7[j][k];
                v[j] = s;
            }
            float na[4];
            #pragma unroll
            for (int j = 0; j < 4; j++) na[j] = fmaxf(sqrtf(v[j]), 1e-8f);
            #pragma unroll
            for (int j = 0; j < 3; j++)
                g_cos[b * 3 + j] = v[4 + j] / (na[j] * na[j + 1]);

            const float fn0 = feat_norm[b * NF];     // feat_norm[b,0,0]
            const bool cond = fn0 > 0.0f;            // TAO = 0
            const float wgt = 1.0f / (expf(fn0) + 1e-10f);
            out[1 + b] = cond ? wgt : 0.0f;          // also encodes cond (wgt>0)
        }
        __syncthreads();   // sm7 reused by img reduction below
    }

    // ---------------- img chunk: uniform 4096 float4 per block ------------
    {
        const int start = blockIdx.x * CH;
        const int batch_lo = start / PIX4;
        const int boundary = (batch_lo + 1) * PIX4;    // may exceed start+CH
        const bool crosses = boundary < start + CH;
        // element g of frame f lives at img[g + (3*batch + f)*PIX4]
        const float4* baseA = img + (size_t)3 * batch_lo * PIX4;
        const float4* baseB = baseA + 3 * PIX4;

        float sA1 = 0.f, sA2 = 0.f, sA3 = 0.f;
        float sB1 = 0.f, sB2 = 0.f, sB3 = 0.f;
        int nqA = 0, nqB = 0;

        #pragma unroll 2
        for (int k = 0; k < 16; k += 2) {
            const int g1 = start + k * TPB + threadIdx.x;
            const int g2 = g1 + TPB;
            const bool hi1 = g1 >= boundary;
            const bool hi2 = g2 >= boundary;
            const float4* p1 = hi1 ? baseB : baseA;
            const float4* p2 = hi2 ? baseB : baseA;

            // 8 independent LDG.128 in flight before any compute.
            float4 a0 = __ldcs(p1 + g1);
            float4 a1 = __ldcs(p1 + g1 + PIX4);
            float4 a2 = __ldcs(p1 + g1 + 2 * PIX4);
            float4 a3 = __ldcs(p1 + g1 + 3 * PIX4);
            float4 b0 = __ldcs(p2 + g2);
            float4 b1 = __ldcs(p2 + g2 + PIX4);
            float4 b2 = __ldcs(p2 + g2 + 2 * PIX4);
            float4 b3 = __ldcs(p2 + g2 + 3 * PIX4);

            float t1, t2, t3; int m;
            group_terms(a0, a1, a2, a3, t1, t2, t3, m);
            if (hi1) { sB1 += t1; sB2 += t2; sB3 += t3; nqB |= m; }
            else     { sA1 += t1; sA2 += t2; sA3 += t3; nqA |= m; }

            group_terms(b0, b1, b2, b3, t1, t2, t3, m);
            if (hi2) { sB1 += t1; sB2 += t2; sB3 += t3; nqB |= m; }
            else     { sA1 += t1; sA2 += t2; sA3 += t3; nqA |= m; }
        }

        // Fused block reduction: 6 float sums + packed neq masks.
        int nqp = nqA | (nqB << 16);
        #pragma unroll
        for (int off = 16; off; off >>= 1) {
            sA1 += __shfl_down_sync(0xffffffffu, sA1, off);
            sA2 += __shfl_down_sync(0xffffffffu, sA2, off);
            sA3 += __shfl_down_sync(0xffffffffu, sA3, off);
            sB1 += __shfl_down_sync(0xffffffffu, sB1, off);
            sB2 += __shfl_down_sync(0xffffffffu, sB2, off);
            sB3 += __shfl_down_sync(0xffffffffu, sB3, off);
            nqp |= __shfl_down_sync(0xffffffffu, nqp, off);
        }
        if (l == 0) {
            sm7[0][w] = sA1; sm7[1][w] = sA2; sm7[2][w] = sA3;
            sm7[3][w] = sB1; sm7[4][w] = sB2; sm7[5][w] = sB3;
            smn[w] = nqp;
        }
        __syncthreads();
        if (threadIdx.x == 0) {
            float v[6];
            int nq = 0;
            #pragma unroll
            for (int j = 0; j < 6; j++) {
                float s = 0.f;
                #pragma unroll
                for (int k = 0; k < TPB / 32; k++) s += sm7[j][k];
                v[j] = s;
            }
            #pragma unroll
            for (int k = 0; k < TPB / 32; k++) nq |= smn[k];

            atomicAdd(&g_part[batch_lo * 3 + 0], v[0]);
            atomicAdd(&g_part[batch_lo * 3 + 1], v[1]);
            atomicAdd(&g_part[batch_lo * 3 + 2], v[2]);
            atomicOr(&g_neq[batch_lo], nq & 0x7);
            if (crosses) {
                const int bh = batch_lo + 1;
                atomicAdd(&g_part[bh * 3 + 0], v[3]);
                atomicAdd(&g_part[bh * 3 + 1], v[4]);
                atomicAdd(&g_part[bh * 3 + 2], v[5]);
                atomicOr(&g_neq[bh], (nq >> 16) & 0x7);
            }
        }
    }

    // ---------------- elect last-finished block for the epilogue ----------
    __syncthreads();
    if (threadIdx.x == 0) {
        __threadfence();
        int old = atomicAdd(&g_ctr, 1);
        s_last = (old == GRID - 1) ? 1 : 0;
    }
    __syncthreads();
    if (!s_last) return;

    __threadfence();  // acquire: all other blocks' atomics/stores visible

    // thread b handles batch b (256 threads == NB)
    const int b = threadIdx.x;
    float pen = 0.0f;
    {
        const float outw = out[1 + b];   // cond ? wgt : 0
        const float dsq0 = g_part[b * 3 + 0];
        const float dsq1 = g_part[b * 3 + 1];
        const float dsq2 = g_part[b * 3 + 2];
        const int nqm = g_neq[b];
        const float dsq[3] = {dsq0, dsq1, dsq2};
        #pragma unroll
        for (int j = 0; j < 3; j++) {
            float img_diff = sqrtf(dsq[j]) + 1e-10f;
            float ratio = (1.0f - g_cos[b * 3 + j]) / img_diff;  // LIP = 0
            float term = fmaxf(ratio, 0.0f) * outw;              // SQUARED = false
            if ((nqm >> j) & 1) pen += term;                     // outw==0 covers !cond
        }
    }

    // Reset scratch for the next graph replay (deterministic state).
    g_part[b * 3 + 0] = 0.f;
    g_part[b * 3 + 1] = 0.f;
    g_part[b * 3 + 2] = 0.f;
    g_neq[b] = 0;

    #pragma unroll
    for (int off = 16; off; off >>= 1)
        pen += __shfl_down_sync(0xffffffffu, pen, off);

    __shared__ float smr[TPB / 32];
    if (l == 0) smr[w] = pen;
    __syncthreads();
    if (threadIdx.x == 0) {
        float s = 0.f;
        #pragma unroll
        for (int k = 0; k < TPB / 32; k++) s += smr[k];
        out[0] = s * (1.0f / (float)NB);   // LAMB_LIP = 1
        g_ctr = 0;                          // reset for next replay
    }
}

extern "C" void kernel_launch(void* const* d_in, const int* in_sizes, int n_in,
                              void* d_out, int out_size) {
    const float4* img = (const float4*)d_in[0];
    const float* feat = (const float*)d_in[1];
    const float* feat_norm = (const float*)d_in[2];
    float* out = (float*)d_out;

    fused_kernel<<<GRID, TPB>>>(img, feat, feat_norm, out);
}